// round 5
// baseline (speedup 1.0000x reference)
#include <cuda_runtime.h>
#include <cuda_bf16.h>
#include <cstdint>

// Problem constants (fixed for MoEDense_10411000726246)
#define TB 8192     // batch
#define DD 128      // input dim (K)
#define FF 128      // output dim (N)
#define TT 64       // num experts
#define TM 64       // rows per GEMM tile
#define NBLK 32     // sort blocks
#define CONVBLK 128 // convert blocks

#define MAX_TILES (TB / TM + TT)        // 192
#define PAD_CAP   (TB + TT * TM)        // 12288

// Scratch (no allocations allowed)
__device__ int g_partial[NBLK * TT];
__device__ int g_arrive = 0;
__device__ int g_depart = 0;
__device__ int g_tileExpert[MAX_TILES];
__device__ int g_tileBase[MAX_TILES];
__device__ int g_tileRows[MAX_TILES];
__device__ int g_rowOrder[PAD_CAP];

// Pre-converted bf16 hi/lo operands (X gets one extra all-zero row at TB)
__device__ __nv_bfloat16 g_Xhi[(TB + 1) * DD];
__device__ __nv_bfloat16 g_Xlo[(TB + 1) * DD];
__device__ __nv_bfloat16 g_Whi[TT * DD * FF];
__device__ __nv_bfloat16 g_Wlo[TT * DD * FF];

// ---------------------------------------------------------------------------
__device__ __forceinline__ uint32_t smem_u32(const void* p) {
    uint32_t a;
    asm("{ .reg .u64 t; cvta.to.shared.u64 t, %1; cvt.u32.u64 %0, t; }"
        : "=r"(a) : "l"(p));
    return a;
}

__device__ __forceinline__ void split4(float4 v, uint2& h, uint2& l) {
    __nv_bfloat162 h01 = __float22bfloat162_rn(make_float2(v.x, v.y));
    __nv_bfloat162 h23 = __float22bfloat162_rn(make_float2(v.z, v.w));
    float2 f01 = __bfloat1622float2(h01);
    float2 f23 = __bfloat1622float2(h23);
    __nv_bfloat162 l01 = __float22bfloat162_rn(
        make_float2(v.x - f01.x, v.y - f01.y));
    __nv_bfloat162 l23 = __float22bfloat162_rn(
        make_float2(v.z - f23.x, v.w - f23.y));
    h = make_uint2(*(uint32_t*)&h01, *(uint32_t*)&h23);
    l = make_uint2(*(uint32_t*)&l01, *(uint32_t*)&l23);
}

#define CP_ASYNC16(dst, src)                                                  \
    asm volatile("cp.async.cg.shared.global [%0], [%1], 16;"                  \
                 :: "r"(dst), "l"(src) : "memory")
#define CP_COMMIT_WAIT()                                                      \
    asm volatile("cp.async.commit_group;\n\tcp.async.wait_group 0;"           \
                 ::: "memory")

#define LDSM_X4(r0, r1, r2, r3, addr)                                         \
    asm volatile("ldmatrix.sync.aligned.m8n8.x4.shared.b16 "                  \
                 "{%0,%1,%2,%3}, [%4];"                                       \
                 : "=r"(r0), "=r"(r1), "=r"(r2), "=r"(r3) : "r"(addr))

#define LDSM_X4_T(r0, r1, r2, r3, addr)                                       \
    asm volatile("ldmatrix.sync.aligned.m8n8.x4.trans.shared.b16 "            \
                 "{%0,%1,%2,%3}, [%4];"                                       \
                 : "=r"(r0), "=r"(r1), "=r"(r2), "=r"(r3) : "r"(addr))

#define MMA_16816(d, a0, a1, a2, a3, b0, b1)                                  \
    asm volatile("mma.sync.aligned.m16n8k16.row.col.f32.bf16.bf16.f32 "       \
                 "{%0,%1,%2,%3}, {%4,%5,%6,%7}, {%8,%9}, {%0,%1,%2,%3};"      \
                 : "+f"((d)[0]), "+f"((d)[1]), "+f"((d)[2]), "+f"((d)[3])     \
                 : "r"(a0), "r"(a1), "r"(a2), "r"(a3), "r"(b0), "r"(b1))

// ---------------------------------------------------------------------------
// K_prep: blocks [0,32) = fused histogram/scan/plan/scatter (grid barrier
// among themselves); blocks [32,160) = fp32 -> bf16 hi/lo convert of X and W.
// ---------------------------------------------------------------------------
__global__ __launch_bounds__(256) void k_prep(const int* __restrict__ tidx,
                                              const float* __restrict__ X,
                                              const float* __restrict__ W) {
    int t = threadIdx.x;
    int b = blockIdx.x;

    if (b >= NBLK) {
        // ---- convert path ----
        int cb = b - NBLK;
        if (cb == 0 && t < 64) {   // zero the padding row TB
            ((uint32_t*)(g_Xhi + TB * DD))[t] = 0;
            ((uint32_t*)(g_Xlo + TB * DD))[t] = 0;
        }
        const int XF4 = TB * DD / 4;        // 262144
        const int WF4 = TT * DD * FF / 4;   // 262144
        uint2* xh = (uint2*)g_Xhi; uint2* xl = (uint2*)g_Xlo;
        uint2* wh = (uint2*)g_Whi; uint2* wl = (uint2*)g_Wlo;
        for (int i = cb * 256 + t; i < XF4 + WF4; i += CONVBLK * 256) {
            uint2 h, l;
            if (i < XF4) {
                split4(((const float4*)X)[i], h, l);
                xh[i] = h; xl[i] = l;
            } else {
                int j = i - XF4;
                split4(((const float4*)W)[j], h, l);
                wh[j] = h; wl[j] = l;
            }
        }
        return;
    }

    // ---- sort path (blocks 0..31) ----
    __shared__ int s_bins[TT];
    __shared__ int s_total[TT];
    __shared__ int s_base[TT];
    __shared__ int s_roff[TT];
    __shared__ int s_toff[TT];
    __shared__ int s_ntiles;

    if (t < TT) s_bins[t] = 0;
    __syncthreads();

    int row = b * 256 + t;
    int e = tidx[row];
    e = min(max(e, 0), TT - 1);
    int loc = atomicAdd(&s_bins[e], 1);
    __syncthreads();

    if (t < TT) g_partial[b * TT + t] = s_bins[t];
    __threadfence();
    __syncthreads();

    if (t == 0) {
        atomicAdd(&g_arrive, 1);
        while (atomicAdd(&g_arrive, 0) < NBLK) { }
    }
    __syncthreads();
    __threadfence();

    if (t < TT) {
        int tot = 0, mybase = 0;
        #pragma unroll 4
        for (int i = 0; i < NBLK; i++) {
            int p = g_partial[i * TT + t];
            if (i < b) mybase += p;
            tot += p;
        }
        s_total[t] = tot;
        s_base[t] = mybase;
    }
    __syncthreads();

    if (t == 0) {
        int roff = 0, toff = 0;
        #pragma unroll
        for (int i = 0; i < TT; i++) {
            s_roff[i] = roff;
            s_toff[i] = toff;
            int nt = (s_total[i] + TM - 1) / TM;
            roff += nt * TM;
            toff += nt;
        }
        s_ntiles = toff;
    }
    __syncthreads();

    if (t < TT) s_base[t] += s_roff[t];
    __syncthreads();

    g_rowOrder[s_base[e] + loc] = row;

    if (b == 0) {
        if (t < TT) {
            int tot = s_total[t];
            int nt = (tot + TM - 1) / TM;
            int tb = s_toff[t];
            int rb = s_roff[t];
            for (int j = 0; j < nt; j++) {
                g_tileExpert[tb + j] = t;
                g_tileBase[tb + j]   = rb + j * TM;
                g_tileRows[tb + j]   = min(TM, tot - j * TM);
            }
        }
        __syncthreads();
        for (int idx = s_ntiles + t; idx < MAX_TILES; idx += 256)
            g_tileExpert[idx] = -1;
    }

    if (t == 0) {
        int d = atomicAdd(&g_depart, 1);
        if (d == NBLK - 1) { g_arrive = 0; g_depart = 0; __threadfence(); }
    }
}

// ---------------------------------------------------------------------------
// K_gemm: 64x128 tile per CTA, 256 threads = 8 warps (2M x 4N), warp 32x32.
// Pre-converted bf16 operands streamed with cp.async. 3 HMMA passes:
// D = Ahi*Bhi + Alo*Bhi + Ahi*Blo (fp32 reg accum).
// ---------------------------------------------------------------------------
#define SPAD 136
#define ROWB (SPAD * 2)                  // 272 bytes
#define SM_A_HI 0
#define SM_A_LO (SM_A_HI + TM * ROWB)    // 17408
#define SM_B_HI (SM_A_LO + TM * ROWB)    // 34816
#define SM_B_LO (SM_B_HI + DD * ROWB)    // 69632
#define SM_BIAS (SM_B_LO + DD * ROWB)    // 104448
#define SM_ROWS (SM_BIAS + FF * 4)       // 104960
#define SM_TOTAL (SM_ROWS + TM * 4)      // 105216

__global__ __launch_bounds__(256, 2)
void k_gemm(const float* __restrict__ Bias, float* __restrict__ Y) {
    extern __shared__ char smem[];
    const uint32_t sbase = smem_u32(smem);

    int tile = blockIdx.x;
    int e = g_tileExpert[tile];
    if (e < 0) return;
    int base  = g_tileBase[tile];
    int nrows = g_tileRows[tile];
    int tid = threadIdx.x;
    int wid = tid >> 5;
    int lid = tid & 31;

    int* rows_s   = (int*)(smem + SM_ROWS);
    float* bias_s = (float*)(smem + SM_BIAS);

    if (tid < TM) rows_s[tid] = (tid < nrows) ? g_rowOrder[base + tid] : -1;
    if (tid >= 128) bias_s[tid - 128] = Bias[e * FF + (tid - 128)];

    // --- B: cp.async 128 k-rows x 16 chunks, hi then lo (no dependency)
    {
        const char* WhiB = (const char*)(g_Whi + (size_t)e * DD * FF);
        const char* WloB = (const char*)(g_Wlo + (size_t)e * DD * FF);
        #pragma unroll
        for (int it = 0; it < 16; it++) {
            int idx = tid + it * 256;          // 4096
            int k     = (idx & 2047) >> 4;
            int chunk = idx & 15;
            uint32_t soff = (uint32_t)(k * 256 + chunk * 16);
            uint32_t doff = (uint32_t)(k * ROWB + chunk * 16);
            if (idx < 2048) CP_ASYNC16(sbase + SM_B_HI + doff, WhiB + soff);
            else            CP_ASYNC16(sbase + SM_B_LO + doff, WloB + soff);
        }
    }
    __syncthreads();   // rows_s ready

    // --- A: cp.async 64 rows x 16 chunks, hi + lo (padding -> zero row TB)
    {
        #pragma unroll
        for (int it = 0; it < 8; it++) {
            int idx = tid + it * 256;          // 2048
            int m     = (idx & 1023) >> 4;
            int chunk = idx & 15;
            int r = rows_s[m];
            int r2 = (r < 0) ? TB : r;
            uint32_t soff = (uint32_t)(r2 * 256 + chunk * 16);
            uint32_t doff = (uint32_t)(m * ROWB + chunk * 16);
            if (idx < 1024)
                CP_ASYNC16(sbase + SM_A_HI + doff, (const char*)g_Xhi + soff);
            else
                CP_ASYNC16(sbase + SM_A_LO + doff, (const char*)g_Xlo + soff);
        }
    }
    CP_COMMIT_WAIT();
    __syncthreads();

    // --- Warp tiling: 8 warps = 2(M) x 4(N); warp tile 32x32
    int warpM = wid >> 2;
    int warpN = wid & 3;

    float acc[2][4][4];
    #pragma unroll
    for (int mi = 0; mi < 2; mi++)
        #pragma unroll
        for (int nn = 0; nn < 4; nn++)
            #pragma unroll
            for (int q = 0; q < 4; q++) acc[mi][nn][q] = 0.f;

    uint32_t aLane = (uint32_t)((warpM * 32 + (lid & 15)) * ROWB
                   + (lid >> 4) * 16);
    uint32_t bLane = (uint32_t)((lid & 15) * ROWB
                   + (warpN * 32 + (lid >> 4) * 8) * 2);

    const uint32_t aOff[3] = { SM_A_HI, SM_A_LO, SM_A_HI };
    const uint32_t bOff[3] = { SM_B_HI, SM_B_HI, SM_B_LO };

    #pragma unroll
    for (int p = 0; p < 3; p++) {
        uint32_t aBase = sbase + aOff[p] + aLane;
        uint32_t bBase = sbase + bOff[p] + bLane;
        #pragma unroll
        for (int k0 = 0; k0 < DD; k0 += 16) {
            uint32_t a[2][4];
            #pragma unroll
            for (int mi = 0; mi < 2; mi++)
                LDSM_X4(a[mi][0], a[mi][1], a[mi][2], a[mi][3],
                        aBase + mi * 16 * ROWB + k0 * 2);
            uint32_t bfr[2][4];
            #pragma unroll
            for (int jn = 0; jn < 2; jn++)
                LDSM_X4_T(bfr[jn][0], bfr[jn][1], bfr[jn][2], bfr[jn][3],
                          bBase + k0 * ROWB + jn * 32);
            #pragma unroll
            for (int mi = 0; mi < 2; mi++)
                #pragma unroll
                for (int jn = 0; jn < 2; jn++) {
                    MMA_16816(acc[mi][jn * 2],
                              a[mi][0], a[mi][1], a[mi][2], a[mi][3],
                              bfr[jn][0], bfr[jn][1]);
                    MMA_16816(acc[mi][jn * 2 + 1],
                              a[mi][0], a[mi][1], a[mi][2], a[mi][3],
                              bfr[jn][2], bfr[jn][3]);
                }
        }
    }

    // --- Epilogue: c-frag layout -> gmem with bias
    int colBase = warpN * 32 + (lid & 3) * 2;
    #pragma unroll
    for (int mi = 0; mi < 2; mi++) {
        int row0 = warpM * 32 + mi * 16 + (lid >> 2);
        int gr0 = rows_s[row0];
        int gr1 = rows_s[row0 + 8];
        #pragma unroll
        for (int nn = 0; nn < 4; nn++) {
            int col = colBase + nn * 8;
            float bx = bias_s[col], by = bias_s[col + 1];
            if (gr0 >= 0) {
                float2 o = make_float2(acc[mi][nn][0] + bx,
                                       acc[mi][nn][1] + by);
                *(float2*)&Y[(size_t)gr0 * FF + col] = o;
            }
            if (gr1 >= 0) {
                float2 o = make_float2(acc[mi][nn][2] + bx,
                                       acc[mi][nn][3] + by);
                *(float2*)&Y[(size_t)gr1 * FF + col] = o;
            }
        }
    }
}

// ---------------------------------------------------------------------------
extern "C" void kernel_launch(void* const* d_in, const int* in_sizes, int n_in,
                              void* d_out, int out_size) {
    const float* X    = (const float*)d_in[0];   // [B, D] fp32
    const int*   tidx = (const int*)d_in[1];     // [B] int32
    const float* W    = (const float*)d_in[2];   // [T, D, F] fp32
    const float* Bias = (const float*)d_in[3];   // [T, F] fp32
    float* Y = (float*)d_out;                    // [B, F] fp32

    (void)in_sizes; (void)n_in; (void)out_size;

    cudaFuncSetAttribute(k_gemm, cudaFuncAttributeMaxDynamicSharedMemorySize,
                         SM_TOTAL);

    k_prep<<<NBLK + CONVBLK, 256>>>(tidx, X, W);
    k_gemm<<<MAX_TILES, 256, SM_TOTAL>>>(Bias, Y);
}

// round 6
// speedup vs baseline: 1.1929x; 1.1929x over previous
#include <cuda_runtime.h>
#include <cuda_fp16.h>
#include <cstdint>

// Problem constants (fixed for MoEDense_10411000726246)
#define TB 8192     // batch
#define DD 128      // input dim (K)
#define FF 128      // output dim (N)
#define TT 64       // num experts
#define TM 64       // rows per GEMM tile
#define NBLK 32     // sort blocks
#define CONVBLK 116 // convert blocks (NBLK+CONVBLK=148 = one full wave)

#define MAX_TILES (TB / TM + TT)        // 192
#define PAD_CAP   (TB + TT * TM)        // 12288

// Scratch (no allocations allowed)
__device__ int g_partial[NBLK * TT];
__device__ int g_arrive = 0;
__device__ int g_depart = 0;
__device__ int g_tileExpert[MAX_TILES];
__device__ int g_tileBase[MAX_TILES];
__device__ int g_tileRows[MAX_TILES];
__device__ int g_rowOrder[PAD_CAP];

// Pre-converted operands:
//  g_Xs[row][0..127]=fp16 hi, [128..255]=fp16 lo   (+1 zero pad row at TB)
//  g_Wh = fp16(W)
__device__ __half g_Xs[(TB + 1) * 256];
__device__ __half g_Wh[TT * DD * FF];

// ---------------------------------------------------------------------------
__device__ __forceinline__ uint32_t smem_u32(const void* p) {
    uint32_t a;
    asm("{ .reg .u64 t; cvta.to.shared.u64 t, %1; cvt.u32.u64 %0, t; }"
        : "=r"(a) : "l"(p));
    return a;
}

#define CP_ASYNC16(dst, src)                                                  \
    asm volatile("cp.async.cg.shared.global [%0], [%1], 16;"                  \
                 :: "r"(dst), "l"(src) : "memory")
#define CP_COMMIT_WAIT()                                                      \
    asm volatile("cp.async.commit_group;\n\tcp.async.wait_group 0;"           \
                 ::: "memory")

#define LDSM_X4(r0, r1, r2, r3, addr)                                         \
    asm volatile("ldmatrix.sync.aligned.m8n8.x4.shared.b16 "                  \
                 "{%0,%1,%2,%3}, [%4];"                                       \
                 : "=r"(r0), "=r"(r1), "=r"(r2), "=r"(r3) : "r"(addr))

#define LDSM_X4_T(r0, r1, r2, r3, addr)                                       \
    asm volatile("ldmatrix.sync.aligned.m8n8.x4.trans.shared.b16 "            \
                 "{%0,%1,%2,%3}, [%4];"                                       \
                 : "=r"(r0), "=r"(r1), "=r"(r2), "=r"(r3) : "r"(addr))

#define MMA_16816_F16(d, a0, a1, a2, a3, b0, b1)                              \
    asm volatile("mma.sync.aligned.m16n8k16.row.col.f32.f16.f16.f32 "         \
                 "{%0,%1,%2,%3}, {%4,%5,%6,%7}, {%8,%9}, {%0,%1,%2,%3};"      \
                 : "+f"((d)[0]), "+f"((d)[1]), "+f"((d)[2]), "+f"((d)[3])     \
                 : "r"(a0), "r"(a1), "r"(a2), "r"(a3), "r"(b0), "r"(b1))

// Split fp32x4 -> fp16 hi (returned in h) and fp16 lo (in l)
__device__ __forceinline__ void split4h(float4 v, uint2& h, uint2& l) {
    __half2 h01 = __float22half2_rn(make_float2(v.x, v.y));
    __half2 h23 = __float22half2_rn(make_float2(v.z, v.w));
    float2 f01 = __half22float2(h01);
    float2 f23 = __half22float2(h23);
    __half2 l01 = __float22half2_rn(make_float2(v.x - f01.x, v.y - f01.y));
    __half2 l23 = __float22half2_rn(make_float2(v.z - f23.x, v.w - f23.y));
    h = make_uint2(*(uint32_t*)&h01, *(uint32_t*)&h23);
    l = make_uint2(*(uint32_t*)&l01, *(uint32_t*)&l23);
}

// ---------------------------------------------------------------------------
// K_prep: blocks [0,32) = fused histogram/scan/plan/scatter (grid barrier
// among themselves); blocks [32,148) = fp32 -> fp16 convert of X (hi|lo
// interleaved per row) and W (single fp16).
// ---------------------------------------------------------------------------
__global__ __launch_bounds__(256) void k_prep(const int* __restrict__ tidx,
                                              const float* __restrict__ X,
                                              const float* __restrict__ W) {
    int t = threadIdx.x;
    int b = blockIdx.x;

    if (b >= NBLK) {
        // ---- convert path ----
        int cb = b - NBLK;
        if (cb == 0 && t < 128) {   // zero the padding row TB (512B)
            ((uint32_t*)(g_Xs + TB * 256))[t] = 0;
        }
        const int XF4 = TB * DD / 4;        // 262144
        const int WF4 = TT * DD * FF / 4;   // 262144
        for (int i = cb * 256 + t; i < XF4 + WF4; i += CONVBLK * 256) {
            if (i < XF4) {
                int r  = i >> 5;            // row
                int k4 = i & 31;            // k/4
                uint2 h, l;
                split4h(((const float4*)X)[i], h, l);
                *(uint2*)(g_Xs + (size_t)r * 256 + k4 * 4)       = h;
                *(uint2*)(g_Xs + (size_t)r * 256 + 128 + k4 * 4) = l;
            } else {
                int j = i - XF4;
                float4 v = ((const float4*)W)[j];
                __half2 h01 = __float22half2_rn(make_float2(v.x, v.y));
                __half2 h23 = __float22half2_rn(make_float2(v.z, v.w));
                uint2 hv = make_uint2(*(uint32_t*)&h01, *(uint32_t*)&h23);
                *(uint2*)(g_Wh + (size_t)j * 4) = hv;
            }
        }
        return;
    }

    // ---- sort path (blocks 0..31) ----
    __shared__ int s_bins[TT];
    __shared__ int s_total[TT];
    __shared__ int s_base[TT];
    __shared__ int s_roff[TT];
    __shared__ int s_toff[TT];
    __shared__ int s_ntiles;

    if (t < TT) s_bins[t] = 0;
    __syncthreads();

    int row = b * 256 + t;
    int e = tidx[row];
    e = min(max(e, 0), TT - 1);
    int loc = atomicAdd(&s_bins[e], 1);
    __syncthreads();

    if (t < TT) g_partial[b * TT + t] = s_bins[t];
    __threadfence();
    __syncthreads();

    if (t == 0) {
        atomicAdd(&g_arrive, 1);
        while (atomicAdd(&g_arrive, 0) < NBLK) { }
    }
    __syncthreads();
    __threadfence();

    if (t < TT) {
        int tot = 0, mybase = 0;
        #pragma unroll 4
        for (int i = 0; i < NBLK; i++) {
            int p = g_partial[i * TT + t];
            if (i < b) mybase += p;
            tot += p;
        }
        s_total[t] = tot;
        s_base[t] = mybase;
    }
    __syncthreads();

    if (t == 0) {
        int roff = 0, toff = 0;
        #pragma unroll
        for (int i = 0; i < TT; i++) {
            s_roff[i] = roff;
            s_toff[i] = toff;
            int nt = (s_total[i] + TM - 1) / TM;
            roff += nt * TM;
            toff += nt;
        }
        s_ntiles = toff;
    }
    __syncthreads();

    if (t < TT) s_base[t] += s_roff[t];
    __syncthreads();

    g_rowOrder[s_base[e] + loc] = row;

    if (b == 0) {
        if (t < TT) {
            int tot = s_total[t];
            int nt = (tot + TM - 1) / TM;
            int tb = s_toff[t];
            int rb = s_roff[t];
            for (int j = 0; j < nt; j++) {
                g_tileExpert[tb + j] = t;
                g_tileBase[tb + j]   = rb + j * TM;
                g_tileRows[tb + j]   = min(TM, tot - j * TM);
            }
        }
        __syncthreads();
        for (int idx = s_ntiles + t; idx < MAX_TILES; idx += 256)
            g_tileExpert[idx] = -1;
    }

    if (t == 0) {
        int d = atomicAdd(&g_depart, 1);
        if (d == NBLK - 1) { g_arrive = 0; g_depart = 0; __threadfence(); }
    }
}

// ---------------------------------------------------------------------------
// K_gemm: 64x128 tile per CTA, 256 threads = 8 warps (2M x 4N), warp 32x32.
// Single K'=256 pass over A=[Xhi|Xlo] fp16 with B repeating mod 128:
//   D = Ahi*W16 + Alo*W16   (fp32 reg accumulation)
// ---------------------------------------------------------------------------
#define APAD 264                         // A row: 256 fp16 + 8 pad
#define AROWB (APAD * 2)                 // 528 bytes
#define BPAD 136
#define BROWB (BPAD * 2)                 // 272 bytes
#define SM_A   0
#define SM_B   (SM_A + TM * AROWB)       // 33792
#define SM_BIAS (SM_B + DD * BROWB)      // 68608
#define SM_ROWS (SM_BIAS + FF * 4)       // 69120
#define SM_TOTAL (SM_ROWS + TM * 4)      // 69376

__global__ __launch_bounds__(256, 2)
void k_gemm(const float* __restrict__ Bias, float* __restrict__ Y) {
    extern __shared__ char smem[];
    const uint32_t sbase = smem_u32(smem);

    int tile = blockIdx.x;
    int e = g_tileExpert[tile];
    if (e < 0) return;
    int base  = g_tileBase[tile];
    int nrows = g_tileRows[tile];
    int tid = threadIdx.x;
    int wid = tid >> 5;
    int lid = tid & 31;

    int* rows_s   = (int*)(smem + SM_ROWS);
    float* bias_s = (float*)(smem + SM_BIAS);

    if (tid < TM) rows_s[tid] = (tid < nrows) ? g_rowOrder[base + tid] : -1;
    if (tid >= 128) bias_s[tid - 128] = Bias[e * FF + (tid - 128)];

    // --- B: cp.async 128 k-rows x 16 chunks of 16B (fp16 W, 32KB)
    {
        const char* WB = (const char*)(g_Wh + (size_t)e * DD * FF);
        #pragma unroll
        for (int it = 0; it < 8; it++) {
            int idx = tid + it * 256;          // 2048
            int k     = idx >> 4;
            int chunk = idx & 15;
            CP_ASYNC16(sbase + SM_B + (uint32_t)(k * BROWB + chunk * 16),
                       WB + (uint32_t)(k * 256 + chunk * 16));
        }
    }
    __syncthreads();   // rows_s ready

    // --- A: cp.async 64 rows x 32 chunks of 16B (hi|lo row = 512B)
    {
        #pragma unroll
        for (int it = 0; it < 8; it++) {
            int idx = tid + it * 256;          // 2048
            int m     = idx >> 5;
            int chunk = idx & 31;
            int r = rows_s[m];
            int r2 = (r < 0) ? TB : r;
            CP_ASYNC16(sbase + SM_A + (uint32_t)(m * AROWB + chunk * 16),
                       (const char*)g_Xs + (size_t)r2 * 512 + chunk * 16);
        }
    }
    CP_COMMIT_WAIT();
    __syncthreads();

    // --- Warp tiling: 8 warps = 2(M) x 4(N); warp tile 32x32
    int warpM = wid >> 2;
    int warpN = wid & 3;

    float acc[2][4][4];
    #pragma unroll
    for (int mi = 0; mi < 2; mi++)
        #pragma unroll
        for (int nn = 0; nn < 4; nn++)
            #pragma unroll
            for (int q = 0; q < 4; q++) acc[mi][nn][q] = 0.f;

    uint32_t aLane = sbase + SM_A
                   + (uint32_t)((warpM * 32 + (lid & 15)) * AROWB
                   + (lid >> 4) * 16);
    uint32_t bLane = sbase + SM_B
                   + (uint32_t)((lid & 15) * BROWB
                   + (warpN * 32 + (lid >> 4) * 8) * 2);

    #pragma unroll
    for (int k0 = 0; k0 < 256; k0 += 16) {
        int bk = k0 & 127;                 // B wraps (hi and lo share W)
        uint32_t a[2][4];
        #pragma unroll
        for (int mi = 0; mi < 2; mi++)
            LDSM_X4(a[mi][0], a[mi][1], a[mi][2], a[mi][3],
                    aLane + mi * 16 * AROWB + k0 * 2);
        uint32_t bfr[2][4];
        #pragma unroll
        for (int jn = 0; jn < 2; jn++)
            LDSM_X4_T(bfr[jn][0], bfr[jn][1], bfr[jn][2], bfr[jn][3],
                      bLane + bk * BROWB + jn * 32);
        #pragma unroll
        for (int mi = 0; mi < 2; mi++)
            #pragma unroll
            for (int jn = 0; jn < 2; jn++) {
                MMA_16816_F16(acc[mi][jn * 2],
                              a[mi][0], a[mi][1], a[mi][2], a[mi][3],
                              bfr[jn][0], bfr[jn][1]);
                MMA_16816_F16(acc[mi][jn * 2 + 1],
                              a[mi][0], a[mi][1], a[mi][2], a[mi][3],
                              bfr[jn][2], bfr[jn][3]);
            }
    }

    // --- Epilogue: c-frag layout -> gmem with bias
    int colBase = warpN * 32 + (lid & 3) * 2;
    #pragma unroll
    for (int mi = 0; mi < 2; mi++) {
        int row0 = warpM * 32 + mi * 16 + (lid >> 2);
        int gr0 = rows_s[row0];
        int gr1 = rows_s[row0 + 8];
        #pragma unroll
        for (int nn = 0; nn < 4; nn++) {
            int col = colBase + nn * 8;
            float bx = bias_s[col], by = bias_s[col + 1];
            if (gr0 >= 0) {
                float2 o = make_float2(acc[mi][nn][0] + bx,
                                       acc[mi][nn][1] + by);
                *(float2*)&Y[(size_t)gr0 * FF + col] = o;
            }
            if (gr1 >= 0) {
                float2 o = make_float2(acc[mi][nn][2] + bx,
                                       acc[mi][nn][3] + by);
                *(float2*)&Y[(size_t)gr1 * FF + col] = o;
            }
        }
    }
}

// ---------------------------------------------------------------------------
extern "C" void kernel_launch(void* const* d_in, const int* in_sizes, int n_in,
                              void* d_out, int out_size) {
    const float* X    = (const float*)d_in[0];   // [B, D] fp32
    const int*   tidx = (const int*)d_in[1];     // [B] int32
    const float* W    = (const float*)d_in[2];   // [T, D, F] fp32
    const float* Bias = (const float*)d_in[3];   // [T, F] fp32
    float* Y = (float*)d_out;                    // [B, F] fp32

    (void)in_sizes; (void)n_in; (void)out_size;

    cudaFuncSetAttribute(k_gemm, cudaFuncAttributeMaxDynamicSharedMemorySize,
                         SM_TOTAL);

    k_prep<<<NBLK + CONVBLK, 256>>>(tidx, X, W);
    k_gemm<<<MAX_TILES, 256, SM_TOTAL>>>(Bias, Y);
}